// round 7
// baseline (speedup 1.0000x reference)
#include <cuda_runtime.h>

// Problem constants (fixed by reference: B=8, H=512, W=512)
#define HH 512
#define WW 512
constexpr int HW   = HH * WW;        // 262144
constexpr int NPIX = 8 * HW;         // 2097152
constexpr int TPB  = 256;
constexpr int GRID = NPIX / 4 / TPB; // 2048 (one float4-quantum per thread)

__device__ double       g_accum = 0.0;
__device__ unsigned int g_done  = 0;

__device__ __forceinline__ float4 ld4(const float* p) {
    return __ldg(reinterpret_cast<const float4*>(p));
}
__device__ __forceinline__ float clipf(float v) {
    return fminf(fmaxf(v, 1e-10f), 1.0f);
}

__global__ void __launch_bounds__(TPB, 6) flow_loss_k(
    const float* __restrict__ roi,
    const float* __restrict__ hm0,  const float* __restrict__ hm1,  const float* __restrict__ hm2,
    const float* __restrict__ r1pf, const float* __restrict__ r1pb,
    const float* __restrict__ r1nf, const float* __restrict__ r1nb,
    const float* __restrict__ r0f,  const float* __restrict__ r0b,
    const float* __restrict__ r2f,  const float* __restrict__ r2b,
    const float* __restrict__ fA1,  const float* __restrict__ fB1,   // flow_0_1f, flow_1_0b
    const float* __restrict__ fA2,  const float* __restrict__ fB2,   // flow_1_2f, flow_2_1b
    float* __restrict__ out)
{
    const int v  = blockIdx.x * TPB + threadIdx.x;  // vector id (4 pixels)
    const int p  = v << 2;
    const int x4 = p & (WW - 1);            // 0,4,...,508
    const int y  = (p >> 9) & (HH - 1);
    const int bb = p >> 18;

    float acc = 0.0f;

    // ---- stage 1: weight-defining streams (4 x LDG.128) ----
    const float4 r4  = ld4(roi + p);
    const float4 h04 = ld4(hm0 + p);
    const float4 h14 = ld4(hm1 + p);
    const float4 h24 = ld4(hm2 + p);
    const float* R  = (const float*)&r4;
    const float* H0 = (const float*)&h04;
    const float* H1 = (const float*)&h14;
    const float* H2 = (const float*)&h24;

    float wp[4], wn[4];
    #pragma unroll
    for (int j = 0; j < 4; j++) {
        wp[j] = R[j] * (1.0f + fabsf(H0[j] - H1[j]));
        wn[j] = R[j] * (1.0f + fabsf(H1[j] - H2[j]));
    }

    // ---- stage 2: rec streams consumed in pairs (short live ranges) ----
    {
        const float4 u = ld4(r1pf + p), w = ld4(r1pb + p);
        const float* U = (const float*)&u; const float* Wv = (const float*)&w;
        #pragma unroll
        for (int j = 0; j < 4; j++) {
            const float d0 = U[j] - H1[j], d1 = Wv[j] - H1[j];
            acc += wp[j] * 0.25f * (d0 * d0 + d1 * d1);
        }
    }
    {
        const float4 u = ld4(r1nf + p), w = ld4(r1nb + p);
        const float* U = (const float*)&u; const float* Wv = (const float*)&w;
        #pragma unroll
        for (int j = 0; j < 4; j++) {
            const float d0 = U[j] - H1[j], d1 = Wv[j] - H1[j];
            acc += wn[j] * 0.25f * (d0 * d0 + d1 * d1);
        }
    }
    {
        const float4 u = ld4(r0f + p), w = ld4(r0b + p);
        const float* U = (const float*)&u; const float* Wv = (const float*)&w;
        #pragma unroll
        for (int j = 0; j < 4; j++) {
            const float d0 = U[j] - H0[j], d1 = Wv[j] - H0[j];
            acc += wp[j] * 0.5f * (d0 * d0 + d1 * d1);
        }
    }
    {
        const float4 u = ld4(r2f + p), w = ld4(r2b + p);
        const float* U = (const float*)&u; const float* Wv = (const float*)&w;
        #pragma unroll
        for (int j = 0; j < 4; j++) {
            const float d0 = U[j] - H2[j], d1 = Wv[j] - H2[j];
            acc += wn[j] * 0.5f * (d0 * d0 + d1 * d1);
        }
    }

    // ---- stage 3: flow consistency (per-iteration loads, consumed immediately) ----
    float facc[4] = {0.f, 0.f, 0.f, 0.f};
    const int c0 = bb * (9 * HW) + y * WW + x4;   // channel 0 at (y, x4)
    const bool edgeL = (x4 == 0);                 // lane 0 invalid for dx=+1
    const bool edgeR = (x4 == WW - 4);            // lane 3 invalid for dx=-1

    #pragma unroll
    for (int i = 0; i < 9; i++) {
        const int dy = (i < 3) ? 1 : ((i < 6) ? 0 : -1);
        const int m  = i % 3;
        const int dx = (m == 0) ? 1 : ((m == 1) ? 0 : -1);

        const bool vrow = (dy == 1) ? (y >= 1) : ((dy == -1) ? (y <= HH - 2) : true);
        if (!vrow) continue;

        const int ao = c0 + i * HW;
        const int go = c0 + (8 - i) * HW - dy * WW;   // aligned base (dx via lane shift)

        const float4 av1 = ld4(fA1 + ao);
        const float4 av2 = ld4(fA2 + ao);
        const float4 bv1 = ld4(fB1 + go);
        const float4 bv2 = ld4(fB2 + go);
        const float* A1  = (const float*)&av1; const float* A2  = (const float*)&av2;
        const float* Bv1 = (const float*)&bv1; const float* Bv2 = (const float*)&bv2;

        if (dx == 0) {
            #pragma unroll
            for (int j = 0; j < 4; j++) {
                const float d1 = clipf(A1[j]) - clipf(Bv1[j]);
                const float d2 = clipf(A2[j]) - clipf(Bv2[j]);
                facc[j] += d1 * d1 + d2 * d2;
            }
        } else if (dx == 1) {
            if (!edgeL) {
                const float d1 = clipf(A1[0]) - clipf(__ldg(fB1 + go - 1));
                const float d2 = clipf(A2[0]) - clipf(__ldg(fB2 + go - 1));
                facc[0] += d1 * d1 + d2 * d2;
            }
            #pragma unroll
            for (int j = 1; j < 4; j++) {
                const float d1 = clipf(A1[j]) - clipf(Bv1[j - 1]);
                const float d2 = clipf(A2[j]) - clipf(Bv2[j - 1]);
                facc[j] += d1 * d1 + d2 * d2;
            }
        } else {  // dx == -1
            #pragma unroll
            for (int j = 0; j < 3; j++) {
                const float d1 = clipf(A1[j]) - clipf(Bv1[j + 1]);
                const float d2 = clipf(A2[j]) - clipf(Bv2[j + 1]);
                facc[j] += d1 * d1 + d2 * d2;
            }
            if (!edgeR) {
                const float d1 = clipf(A1[3]) - clipf(__ldg(fB1 + go + 4));
                const float d2 = clipf(A2[3]) - clipf(__ldg(fB2 + go + 4));
                facc[3] += d1 * d1 + d2 * d2;
            }
        }
    }
    #pragma unroll
    for (int j = 0; j < 4; j++) acc += facc[j] * R[j] * (1.0f / 9.0f);

    // ---- block reduction: warp shuffle -> shared -> warp 0 -> atomicAdd(double) ----
    __shared__ float sdata[TPB / 32];
    #pragma unroll
    for (int off = 16; off; off >>= 1)
        acc += __shfl_down_sync(0xffffffffu, acc, off);
    const int lane = threadIdx.x & 31;
    const int wid  = threadIdx.x >> 5;
    if (lane == 0) sdata[wid] = acc;
    __syncthreads();

    if (wid == 0) {
        float t = (lane < TPB / 32) ? sdata[lane] : 0.0f;
        #pragma unroll
        for (int off = 4; off; off >>= 1)
            t += __shfl_down_sync(0xffffffffu, t, off);

        if (lane == 0) {
            atomicAdd(&g_accum, (double)t);
            __threadfence();
            const unsigned int ticket = atomicAdd(&g_done, 1u);
            if (ticket == gridDim.x - 1) {
                out[0] = (float)g_accum;
                g_accum = 0.0;          // reset for next graph replay
                __threadfence();
                g_done = 0;
            }
        }
    }
}

extern "C" void kernel_launch(void* const* d_in, const int* in_sizes, int n_in,
                              void* d_out, int out_size) {
    const float* roi  = (const float*)d_in[0];
    // d_in[1] = boundary_mask : unused by the reference loss
    const float* hm0  = (const float*)d_in[2];
    const float* hm1  = (const float*)d_in[3];
    const float* hm2  = (const float*)d_in[4];
    const float* r1pf = (const float*)d_in[5];
    const float* r1pb = (const float*)d_in[6];
    const float* r1nf = (const float*)d_in[7];
    const float* r1nb = (const float*)d_in[8];
    const float* r0f  = (const float*)d_in[9];
    const float* r0b  = (const float*)d_in[10];
    const float* r2f  = (const float*)d_in[11];
    const float* r2b  = (const float*)d_in[12];
    const float* fA1  = (const float*)d_in[13];
    const float* fB1  = (const float*)d_in[14];
    const float* fA2  = (const float*)d_in[15];
    const float* fB2  = (const float*)d_in[16];

    flow_loss_k<<<GRID, TPB>>>(roi, hm0, hm1, hm2,
                               r1pf, r1pb, r1nf, r1nb,
                               r0f, r0b, r2f, r2b,
                               fA1, fB1, fA2, fB2,
                               (float*)d_out);
}